// round 15
// baseline (speedup 1.0000x reference)
#include <cuda_runtime.h>
#include <cuda_bf16.h>
#include <math.h>
#include <stdint.h>

// ---------------- problem constants ----------------
#define Bv   4
#define Rv   4
#define Nv   4096
#define Mv   64
#define KNv  12288
#define BRv  16
#define P1   196608
#define P2   1024
#define Fv   512
#define TILES64 3072
#define TPB64   192
#define NGROUPS 296
#define NBLK 148

// ---------------- device scratch ----------------
__device__ int   d_topk[Bv * Nv * 3];
__device__ float d_csum[Bv * 2 * Mv];
__device__ float d_ccnt[Bv * Mv];
__device__ float d_g[130 * P2];
__device__ float d_fcol0[BRv * 128];
__device__ float d_A[256 * P2];
__device__ float d_B2[256 * P2];
__device__ float d_C2[512 * P2];
__device__ float d_D2[512 * P2];
__device__ int   d_ctr;
__device__ int            d_bcnt = 0;
__device__ volatile int   d_bsense = 0;

// ---------------- grid barrier (148 co-resident blocks) ----------------
__device__ __forceinline__ void gbar(int& ls) {
    __syncthreads();
    if (threadIdx.x == 0) {
        __threadfence();
        int v = atomicAdd(&d_bcnt, 1);
        if (v == NBLK - 1) {
            d_bcnt = 0;
            __threadfence();
            d_bsense = ls;
        } else {
            while (d_bsense != ls) { }
        }
    }
    __syncthreads();
    ls ^= 1;
}

// ---------------- scalar helpers ----------------
__device__ __forceinline__ unsigned long long ffma2(unsigned long long a,
                                                    unsigned long long b,
                                                    unsigned long long c) {
    unsigned long long d;
    asm("fma.rn.f32x2 %0, %1, %2, %3;" : "=l"(d) : "l"(a), "l"(b), "l"(c));
    return d;
}
__device__ __forceinline__ unsigned long long pack2(float lo, float hi) {
    unsigned long long r;
    asm("mov.b64 %0, {%1, %2};" : "=l"(r) : "f"(lo), "f"(hi));
    return r;
}
__device__ __forceinline__ float lo2(unsigned long long a) { return __uint_as_float((unsigned)a); }
__device__ __forceinline__ float hi2(unsigned long long a) { return __uint_as_float((unsigned)(a >> 32)); }

__device__ __forceinline__ void rot_cs(int r, float& c, float& s) {
    float th = 6.2831855f * (float)r * 0.25f;
    c = cosf(th);
    s = sinf(th);
}
__device__ __forceinline__ uint32_t smem_u32(const void* p) {
    uint32_t a;
    asm("{ .reg .u64 t; cvta.to.shared.u64 t, %1; cvt.u32.u64 %0, t; }" : "=r"(a) : "l"(p));
    return a;
}
__device__ __forceinline__ uint32_t swz(uint32_t b) { return b ^ ((b >> 3) & 0x70); }

// ---------------- warp MMA helpers ----------------
__device__ __forceinline__ void ldsm4(uint32_t* r, uint32_t addr) {
    asm volatile("ldmatrix.sync.aligned.m8n8.x4.shared.b16 {%0,%1,%2,%3}, [%4];"
                 : "=r"(r[0]), "=r"(r[1]), "=r"(r[2]), "=r"(r[3]) : "r"(addr));
}
__device__ __forceinline__ void mma16816(float* d, const uint32_t* a, const uint32_t* b) {
    asm volatile("mma.sync.aligned.m16n8k16.row.col.f32.bf16.bf16.f32 "
                 "{%0,%1,%2,%3}, {%4,%5,%6,%7}, {%8,%9}, {%0,%1,%2,%3};"
                 : "+f"(d[0]), "+f"(d[1]), "+f"(d[2]), "+f"(d[3])
                 : "r"(a[0]), "r"(a[1]), "r"(a[2]), "r"(a[3]), "r"(b[0]), "r"(b[1]));
}

template<int NT>
__device__ __forceinline__ void mma3p(float acc[][4], uint32_t aHb, uint32_t aLb,
                                      uint32_t wHb, uint32_t wLb, int mt0, int n0, int lane) {
    const int abase = (lane & 7) + ((lane >> 3) & 1) * 8;
    const int aoff = ((lane >> 4) & 1) * 16;
    const int arow0 = 16 * mt0 + abase;
    const int arow1 = arow0 + 16;
    const int brow = (lane & 7) + (lane >> 4) * 8;
    const int boff = ((lane >> 3) & 1) * 16;
    #pragma unroll
    for (int ks = 0; ks < 4; ks++) {
        uint32_t aH0[4], aL0[4], aH1[4], aL1[4];
        uint32_t a0s = swz((uint32_t)(arow0 * 128 + 32 * ks + aoff));
        uint32_t a1s = swz((uint32_t)(arow1 * 128 + 32 * ks + aoff));
        ldsm4(aH0, aHb + a0s);
        ldsm4(aH1, aHb + a1s);
        ldsm4(aL0, aLb + a0s);
        ldsm4(aL1, aLb + a1s);
        uint32_t roffs[NT / 2];
        uint32_t wf[NT / 2][4];
        #pragma unroll
        for (int u = 0; u < NT / 2; u++) {
            roffs[u] = swz((uint32_t)((n0 + 16 * u + brow) * 128 + 32 * ks + boff));
            ldsm4(wf[u], wHb + roffs[u]);
        }
        #pragma unroll
        for (int u = 0; u < NT / 2; u++) {
            mma16816(acc[2 * u],          aH0, wf[u]); mma16816(acc[2 * u + 1],      aH0, wf[u] + 2);
            mma16816(acc[NT + 2 * u],     aH1, wf[u]); mma16816(acc[NT + 2 * u + 1], aH1, wf[u] + 2);
        }
        #pragma unroll
        for (int u = 0; u < NT / 2; u++) {
            mma16816(acc[2 * u],          aL0, wf[u]); mma16816(acc[2 * u + 1],      aL0, wf[u] + 2);
            mma16816(acc[NT + 2 * u],     aL1, wf[u]); mma16816(acc[NT + 2 * u + 1], aL1, wf[u] + 2);
        }
        #pragma unroll
        for (int u = 0; u < NT / 2; u++)
            ldsm4(wf[u], wLb + roffs[u]);
        #pragma unroll
        for (int u = 0; u < NT / 2; u++) {
            mma16816(acc[2 * u],          aH0, wf[u]); mma16816(acc[2 * u + 1],      aH0, wf[u] + 2);
            mma16816(acc[NT + 2 * u],     aH1, wf[u]); mma16816(acc[NT + 2 * u + 1], aH1, wf[u] + 2);
        }
    }
}

__device__ __forceinline__ void st_pair(uint32_t hB, uint32_t lB, int p, int o,
                                        float v0, float v1) {
    uint32_t h, l;
    asm("cvt.rn.bf16x2.f32 %0, %1, %2;" : "=r"(h) : "f"(v1), "f"(v0));
    float h0 = __uint_as_float(h << 16);
    float h1 = __uint_as_float(h & 0xffff0000u);
    asm("cvt.rn.bf16x2.f32 %0, %1, %2;" : "=r"(l) : "f"(v1 - h1), "f"(v0 - h0));
    uint32_t off = swz((uint32_t)(p * 128 + 2 * o));
    asm volatile("st.shared.b32 [%0], %1;" :: "r"(hB + off), "r"(h) : "memory");
    asm volatile("st.shared.b32 [%0], %1;" :: "r"(lB + off), "r"(l) : "memory");
}

__device__ __forceinline__ void pack_store8(uint32_t addrH, uint32_t addrL, const float* v) {
    uint32_t h[4], l[4];
    #pragma unroll
    for (int q = 0; q < 4; q++) {
        float a = v[2 * q], b = v[2 * q + 1];
        asm("cvt.rn.bf16x2.f32 %0, %1, %2;" : "=r"(h[q]) : "f"(b), "f"(a));
        float ha = __uint_as_float(h[q] << 16);
        float hb = __uint_as_float(h[q] & 0xffff0000u);
        asm("cvt.rn.bf16x2.f32 %0, %1, %2;" : "=r"(l[q]) : "f"(b - hb), "f"(a - ha));
    }
    asm volatile("st.shared.v4.b32 [%0], {%1, %2, %3, %4};"
                 :: "r"(addrH), "r"(h[0]), "r"(h[1]), "r"(h[2]), "r"(h[3]) : "memory");
    asm volatile("st.shared.v4.b32 [%0], {%1, %2, %3, %4};"
                 :: "r"(addrL), "r"(l[0]), "r"(l[1]), "r"(l[2]), "r"(l[3]) : "memory");
}

// ---------------- fused fp kernel: init + topk + MMA MLP + scatter-max -----
#define OW1H  0
#define OW1L  8192
#define OW2H  16384
#define OW2L  32768
#define OW3AH 49152
#define OW3AL 65536
#define OW3BH 81920
#define OW3BL 98304
#define OGRP  114688
#define OW0F  212992
#define OW3X  213504
#define OB0   214528
#define OB1   214784
#define OB2   215040
#define OB3   215552
#define OXS   216064
#define OMS   217088
#define ONRT  217600
#define OTS   225792
#define SMEM_TC 225824

__global__ void __launch_bounds__(512, 1) k_fp_mma(
    const float* __restrict__ x, const float* __restrict__ node,
    const float* __restrict__ W0, const float* __restrict__ b0,
    const float* __restrict__ W1, const float* __restrict__ b1,
    const float* __restrict__ W2, const float* __restrict__ b2,
    const float* __restrict__ W3, const float* __restrict__ b3)
{
    extern __shared__ __align__(1024) char smc[];
    float* smf = (float*)smc;
    const int tid  = threadIdx.x;
    const int wid  = tid >> 5;
    const int lane = tid & 31;
    const uint32_t sb = smem_u32(smc);
    int ls = d_bsense ^ 1;

    // ---- phase A: zero accumulators + topk distances (no atomics yet) ----
    const int gtid = blockIdx.x * 512 + tid;
    for (int i = gtid; i < 512 * P2; i += NBLK * 512) {
        if (i < Bv * 2 * Mv) d_csum[i] = 0.f;
        if (i < Bv * Mv)     d_ccnt[i] = 0.f;
        if (i < 130 * P2)    d_g[i]    = 0.f;
        if (i < 256 * P2) { d_A[i] = 0.f; d_B2[i] = 0.f; }
        d_C2[i] = 0.f;
        d_D2[i] = 0.f;
    }
    if (gtid == 0) d_ctr = NGROUPS;

    float tx0 = 0.f, tx1 = 0.f;
    int ti0 = 0, ti1 = 0, ti2 = 0;
    const bool has_pt = (gtid < Bv * Nv);
    if (has_pt) {
        int b = gtid >> 12, n = gtid & (Nv - 1);
        tx0 = x[b * 2 * Nv + n];
        tx1 = x[b * 2 * Nv + Nv + n];
        float d0 = 3.4e38f, d1 = 3.4e38f, d2 = 3.4e38f;
        #pragma unroll
        for (int m = 0; m < Mv; m++) {
            float dx = tx0 - __ldg(&node[b * 2 * Mv + m]);
            float dy = tx1 - __ldg(&node[b * 2 * Mv + Mv + m]);
            float d = dx * dx + dy * dy;
            if (d < d0)      { d2 = d1; ti2 = ti1; d1 = d0; ti1 = ti0; d0 = d; ti0 = m; }
            else if (d < d1) { d2 = d1; ti2 = ti1; d1 = d;  ti1 = m; }
            else if (d < d2) { d2 = d;  ti2 = m; }
        }
        int o = gtid * 3;
        d_topk[o] = ti0; d_topk[o + 1] = ti1; d_topk[o + 2] = ti2;
    }

    // ---- weight conversion (independent of phase A/B) ----
    for (int i = tid; i < 4096; i += 512) {
        int o = i >> 6, k = i & 63;
        float w = W1[o * 64 + k];
        __nv_bfloat16 h = __float2bfloat16(w);
        __nv_bfloat16 l = __float2bfloat16(w - __bfloat162float(h));
        uint32_t off = swz(o * 128 + 2 * k);
        *(__nv_bfloat16*)(smc + OW1H + off) = h;
        *(__nv_bfloat16*)(smc + OW1L + off) = l;
    }
    for (int i = tid; i < 8192; i += 512) {
        int o = i >> 6, k = i & 63;
        float w = W2[o * 64 + k];
        __nv_bfloat16 h = __float2bfloat16(w);
        __nv_bfloat16 l = __float2bfloat16(w - __bfloat162float(h));
        uint32_t off = swz(o * 128 + 2 * k);
        *(__nv_bfloat16*)(smc + OW2H + off) = h;
        *(__nv_bfloat16*)(smc + OW2L + off) = l;
    }
    for (int i = tid; i < 8192; i += 512) {
        int o = i >> 6, k = i & 63;
        float w = W3[o * 130 + 2 + k];
        __nv_bfloat16 h = __float2bfloat16(w);
        __nv_bfloat16 l = __float2bfloat16(w - __bfloat162float(h));
        uint32_t off = swz(o * 128 + 2 * k);
        *(__nv_bfloat16*)(smc + OW3AH + off) = h;
        *(__nv_bfloat16*)(smc + OW3AL + off) = l;
    }
    for (int i = tid; i < 8192; i += 512) {
        int o = i >> 6, k = i & 63;
        float w = W3[o * 130 + 66 + k];
        __nv_bfloat16 h = __float2bfloat16(w);
        __nv_bfloat16 l = __float2bfloat16(w - __bfloat162float(h));
        uint32_t off = swz(o * 128 + 2 * k);
        *(__nv_bfloat16*)(smc + OW3BH + off) = h;
        *(__nv_bfloat16*)(smc + OW3BL + off) = l;
    }
    if (tid < 128) {
        smf[OW0F / 4 + tid] = W0[tid];
        smf[OW3X / 4 + tid]       = W3[tid * 130];
        smf[OW3X / 4 + 128 + tid] = W3[tid * 130 + 1];
        if (tid < 64) { smf[OB0 / 4 + tid] = b0[tid]; smf[OB1 / 4 + tid] = b1[tid]; }
        smf[OB2 / 4 + tid] = b2[tid];
        smf[OB3 / 4 + tid] = b3[tid];
    }

    gbar(ls);   // zeroing complete chip-wide

    // ---- phase B: cluster accumulation atomics ----
    if (has_pt) {
        int b = gtid >> 12;
        atomicAdd(&d_csum[b * 2 * Mv + ti0],      tx0);
        atomicAdd(&d_csum[b * 2 * Mv + Mv + ti0], tx1);
        atomicAdd(&d_ccnt[b * Mv + ti0], 1.f);
        atomicAdd(&d_csum[b * 2 * Mv + ti1],      tx0);
        atomicAdd(&d_csum[b * 2 * Mv + Mv + ti1], tx1);
        atomicAdd(&d_ccnt[b * Mv + ti1], 1.f);
        atomicAdd(&d_csum[b * 2 * Mv + ti2],      tx0);
        atomicAdd(&d_csum[b * 2 * Mv + Mv + ti2], tx1);
        atomicAdd(&d_ccnt[b * Mv + ti2], 1.f);
    }

    gbar(ls);   // csum/ccnt final

    // ---- nrot table ----
    if (tid < 256) {
        int b = tid >> 6, m = tid & 63;
        float cnt = d_ccnt[b * Mv + m];
        float inv = 1.f / (cnt + 1e-5f);
        float m0 = d_csum[b * 2 * Mv + m]      * inv;
        float m1 = d_csum[b * 2 * Mv + Mv + m] * inv;
        #pragma unroll
        for (int r = 0; r < Rv; r++) {
            float cc, ss; rot_cs(r, cc, ss);
            int br = b * Rv + r;
            smf[ONRT / 4 + br * 128 + m]      = cc * m0 - ss * m1;
            smf[ONRT / 4 + br * 128 + 64 + m] = ss * m0 + cc * m1;
        }
    }
    __syncthreads();

    const int grp  = wid >> 3;
    const int tidg = tid & 255;
    const int wg   = wid & 7;
    const int mp   = wg >> 2;
    const int nq   = wg & 3;
    const int mt0  = 2 * mp;
    const int gq   = lane >> 2;
    const int tq   = lane & 3;

    const uint32_t gb  = sb + OGRP + grp * 49152;
    const uint32_t bAH = gb,          bAL = gb + 8192;
    const uint32_t bRH = gb + 16384,  bRL = gb + 24576;
    const uint32_t bCH = gb + 32768,  bCL = gb + 40960;
    float* xsf = smf + (OXS + grp * 512) / 4;
    int*   ms  = (int*)(smc + OMS + grp * 256);
    int*   tsh = (int*)(smc + OTS + grp * 4);
    const float* nrt = smf + ONRT / 4;
    const int barid = grp + 1;

    #define GBARG() asm volatile("bar.sync %0, 256;" :: "r"(barid) : "memory")

    int t = blockIdx.x * 2 + grp;
    while (t < TILES64) {
        int br = t / TPB64; int tloc = t - br * TPB64; int kn0 = tloc * 64;
        int b = br >> 2, r = br & 3;

        {
            int pp = tidg & 63, q = tidg >> 6;
            int kn = kn0 + pp; int k = kn >> 12; int n = kn & (Nv - 1);
            float x0r = x[b * 2 * Nv + n], x1r = x[b * 2 * Nv + Nv + n];
            float cc, ss; rot_cs(r, cc, ss);
            float xr0 = cc * x0r - ss * x1r;
            float xr1 = ss * x0r + cc * x1r;
            int m = d_topk[(b * Nv + n) * 3 + k];
            float xd0 = xr0 - nrt[br * 128 + m];
            float xd1 = xr1 - nrt[br * 128 + 64 + m];
            if (q == 0) { xsf[pp] = xd0; xsf[64 + pp] = xd1; ms[pp] = m; }
            float v[16];
            #pragma unroll
            for (int j = 0; j < 16; j++) {
                int o = 16 * q + j;
                v[j] = fmaxf(fmaf(smf[OW0F / 4 + 2 * o], xd0,
                             fmaf(smf[OW0F / 4 + 2 * o + 1], xd1, smf[OB0 / 4 + o])), 0.f);
            }
            uint32_t ro = pp * 128 + 32 * q;
            pack_store8(bAH + swz(ro),      bAL + swz(ro),      v);
            pack_store8(bAH + swz(ro + 16), bAL + swz(ro + 16), v + 8);
        }
        GBARG();

        {
            float acc[4][4];
            #pragma unroll
            for (int i = 0; i < 4; i++)
                #pragma unroll
                for (int j = 0; j < 4; j++) acc[i][j] = 0.f;
            int n0 = nq * 16;
            mma3p<2>(acc, bAH, bAL, sb + OW1H, sb + OW1L, mt0, n0, lane);
            #pragma unroll
            for (int mt = 0; mt < 2; mt++) {
                int rp = 16 * (mt0 + mt) + gq;
                #pragma unroll
                for (int nt = 0; nt < 2; nt++) {
                    int o = n0 + 8 * nt + 2 * tq;
                    float bv0 = smf[OB1 / 4 + o], bv1 = smf[OB1 / 4 + o + 1];
                    float* a = acc[mt * 2 + nt];
                    st_pair(bRH, bRL, rp, o,
                            fmaxf(a[0] + bv0, 0.f), fmaxf(a[1] + bv1, 0.f));
                    st_pair(bRH, bRL, rp + 8, o,
                            fmaxf(a[2] + bv0, 0.f), fmaxf(a[3] + bv1, 0.f));
                }
            }
        }
        GBARG();

        {
            float acc[8][4];
            #pragma unroll
            for (int i = 0; i < 8; i++)
                #pragma unroll
                for (int j = 0; j < 4; j++) acc[i][j] = 0.f;
            int n0 = nq * 32;
            mma3p<4>(acc, bRH, bRL, sb + OW2H, sb + OW2L, mt0, n0, lane);
            uint32_t hB = (nq < 2) ? bAH : bCH;
            uint32_t lB = (nq < 2) ? bAL : bCL;
            #pragma unroll
            for (int mt = 0; mt < 2; mt++) {
                int rp = 16 * (mt0 + mt) + gq;
                #pragma unroll
                for (int nt = 0; nt < 4; nt++) {
                    int o = n0 + 8 * nt + 2 * tq;
                    float bv0 = smf[OB2 / 4 + o], bv1 = smf[OB2 / 4 + o + 1];
                    int oc = o & 63;
                    float* a = acc[mt * 4 + nt];
                    st_pair(hB, lB, rp, oc,
                            fmaxf(a[0] + bv0, 0.f), fmaxf(a[1] + bv1, 0.f));
                    st_pair(hB, lB, rp + 8, oc,
                            fmaxf(a[2] + bv0, 0.f), fmaxf(a[3] + bv1, 0.f));
                }
            }
        }
        GBARG();

        {
            float acc[8][4];
            #pragma unroll
            for (int i = 0; i < 8; i++)
                #pragma unroll
                for (int j = 0; j < 4; j++) acc[i][j] = 0.f;
            int n0 = nq * 32;
            mma3p<4>(acc, bAH, bAL, sb + OW3AH, sb + OW3AL, mt0, n0, lane);
            mma3p<4>(acc, bCH, bCL, sb + OW3BH, sb + OW3BL, mt0, n0, lane);

            #pragma unroll
            for (int mt = 0; mt < 2; mt++) {
                int rp = 16 * (mt0 + mt) + gq;
                float x0a = xsf[rp],     x1a = xsf[64 + rp];
                float x0b = xsf[rp + 8], x1b = xsf[64 + rp + 8];
                int ma = ms[rp], mb = ms[rp + 8];
                unsigned* gpa = (unsigned*)&d_g[2 * P2 + br * Mv + ma];
                unsigned* gpb = (unsigned*)&d_g[2 * P2 + br * Mv + mb];
                bool put0 = (tloc == 0 && rp == 0);
                #pragma unroll
                for (int nt = 0; nt < 4; nt++) {
                    int o = n0 + 8 * nt + 2 * tq;
                    float w00 = smf[OW3X / 4 + o],     w10 = smf[OW3X / 4 + 128 + o];
                    float w01 = smf[OW3X / 4 + o + 1], w11 = smf[OW3X / 4 + 128 + o + 1];
                    float bv0 = smf[OB3 / 4 + o],      bv1 = smf[OB3 / 4 + o + 1];
                    float* a = acc[mt * 4 + nt];
                    float v0 = fmaxf(a[0] + bv0 + w00 * x0a + w10 * x1a, 0.f);
                    float v1 = fmaxf(a[1] + bv1 + w01 * x0a + w11 * x1a, 0.f);
                    float v2 = fmaxf(a[2] + bv0 + w00 * x0b + w10 * x1b, 0.f);
                    float v3 = fmaxf(a[3] + bv1 + w01 * x0b + w11 * x1b, 0.f);
                    atomicMax(gpa + o * P2,       __float_as_uint(v0));
                    atomicMax(gpa + (o + 1) * P2, __float_as_uint(v1));
                    atomicMax(gpb + o * P2,       __float_as_uint(v2));
                    atomicMax(gpb + (o + 1) * P2, __float_as_uint(v3));
                    if (put0) { d_fcol0[br * 128 + o] = v0; d_fcol0[br * 128 + o + 1] = v1; }
                }
            }
        }
        if (tidg == 0) *tsh = atomicAdd(&d_ctr, 1);
        GBARG();
        t = *tsh;
    }
    #undef GBARG
}

// ---------------- gp persistent kernel: fix + 4 GEMM layers + reduce -------
__device__ void gp_layer(float* Wsh, float* Ish,
                         const float* __restrict__ W,
                         const float* __restrict__ in1, int C1, const float* __restrict__ bias1,
                         const float* __restrict__ in2, int C2, const float* __restrict__ bias2,
                         float* __restrict__ out, int KCH, int nout64, int nkc)
{
    const int C = C1 + C2;
    const int tid = threadIdx.x;
    const int og = tid >> 5;
    const int cg = tid & 31;
    const int o0 = og * 8, p0 = cg * 2;
    const int items = 16 * nout64 * nkc;

    for (int item = blockIdx.x; item < items; item += NBLK) {
        int colt = item & 15;
        int rest = item >> 4;
        int outt = rest % nout64;
        int kc   = rest / nout64;
        int col0 = colt * 64, ob0 = outt * 64;
        int kbase = kc * KCH;
        int kend = (kbase + KCH < C) ? (kbase + KCH) : C;

        unsigned long long acc[8];
        #pragma unroll
        for (int i = 0; i < 8; i++) acc[i] = 0ull;

        for (int k0 = kbase; k0 < kend; k0 += 16) {
            __syncthreads();
            #pragma unroll
            for (int q = 0; q < 4; q++) {
                int l = tid * 4 + q; int oo = l >> 4, kk = l & 15;
                int c = k0 + kk;
                Wsh[kk * 68 + oo] = (c < kend) ? W[(ob0 + oo) * C + c] : 0.f;
            }
            #pragma unroll
            for (int q = 0; q < 4; q++) {
                int l = tid * 4 + q; int kk = l >> 6, cc = l & 63;
                int c = k0 + kk;
                float v = 0.f;
                if (c < kend) {
                    if (c < C1) {
                        v = in1[c * P2 + col0 + cc];
                        if (bias1) v = fmaxf(v + bias1[c], 0.f);
                    } else {
                        v = in2[(c - C1) * P2 + col0 + cc];
                        if (bias2) v = fmaxf(v + bias2[c - C1], 0.f);
                    }
                }
                Ish[kk * 68 + cc] = v;
            }
            __syncthreads();
            #pragma unroll
            for (int kk = 0; kk < 16; kk++) {
                float4 wA = *(const float4*)&Wsh[kk * 68 + o0];
                float4 wB = *(const float4*)&Wsh[kk * 68 + o0 + 4];
                unsigned long long a = *(const unsigned long long*)&Ish[kk * 68 + p0];
                acc[0] = ffma2(pack2(wA.x, wA.x), a, acc[0]);
                acc[1] = ffma2(pack2(wA.y, wA.y), a, acc[1]);
                acc[2] = ffma2(pack2(wA.z, wA.z), a, acc[2]);
                acc[3] = ffma2(pack2(wA.w, wA.w), a, acc[3]);
                acc[4] = ffma2(pack2(wB.x, wB.x), a, acc[4]);
                acc[5] = ffma2(pack2(wB.y, wB.y), a, acc[5]);
                acc[6] = ffma2(pack2(wB.z, wB.z), a, acc[6]);
                acc[7] = ffma2(pack2(wB.w, wB.w), a, acc[7]);
            }
        }
        __syncthreads();
        #pragma unroll
        for (int i = 0; i < 8; i++) {
            int o = ob0 + o0 + i;
            atomicAdd(&out[o * P2 + col0 + p0],     lo2(acc[i]));
            atomicAdd(&out[o * P2 + col0 + p0 + 1], hi2(acc[i]));
        }
    }
}

__global__ void __launch_bounds__(256) k_gp(
    const float* __restrict__ gpW0, const float* __restrict__ gpb0,
    const float* __restrict__ gpW1, const float* __restrict__ gpb1,
    const float* __restrict__ gpW2, const float* __restrict__ gpb2,
    const float* __restrict__ gpW3, const float* __restrict__ gpb3,
    float* __restrict__ out)
{
    __shared__ __align__(16) float Wsh[16 * 68];
    __shared__ __align__(16) float Ish[16 * 68];
    int ls = d_bsense ^ 1;
    const int gtid = blockIdx.x * 256 + threadIdx.x;

    float *p_g = d_g, *p_A = d_A, *p_B2 = d_B2, *p_C2 = d_C2, *p_D2 = d_D2;

    // ---- fix: d_g rows 0/1 + empty-cluster fallback ----
    for (int idx = gtid; idx < BRv * 128 * Mv; idx += NBLK * 256) {
        if (idx < 2048) {
            int m = idx & 63, br = (idx >> 6) & 15, ch = idx >> 10;
            int b = br >> 2, r = br & 3;
            float cnt = d_ccnt[b * Mv + m];
            float inv = 1.f / (cnt + 1e-5f);
            float m0 = d_csum[b * 2 * Mv + m]      * inv;
            float m1 = d_csum[b * 2 * Mv + Mv + m] * inv;
            float cc, ss; rot_cs(r, cc, ss);
            d_g[ch * P2 + br * Mv + m] = ch ? (ss * m0 + cc * m1) : (cc * m0 - ss * m1);
        }
        int m = idx & 63; int c = (idx >> 6) & 127; int br = idx >> 13;
        int b = br >> 2;
        if (d_ccnt[b * Mv + m] == 0.f)
            d_g[(2 + c) * P2 + br * Mv + m] = d_fcol0[br * 128 + c];
    }
    gbar(ls);

    gp_layer(Wsh, Ish, gpW0, p_g, 130, nullptr, nullptr, 0, nullptr, p_A, 65, 4, 2);
    gbar(ls);
    gp_layer(Wsh, Ish, gpW1, p_A, 256, gpb0, nullptr, 0, nullptr, p_B2, 128, 4, 2);
    gbar(ls);
    gp_layer(Wsh, Ish, gpW2, p_B2, 256, gpb1, nullptr, 0, nullptr, p_C2, 128, 8, 2);
    gbar(ls);
    gp_layer(Wsh, Ish, gpW3, p_g, 130, nullptr, p_C2, 512, gpb2, p_D2, 129, 8, 5);
    gbar(ls);

    // ---- reduce: max over (r, m) + fused final bias/relu ----
    if (gtid < Bv * Fv) {
        int b = gtid >> 9, f = gtid & 511;
        const float* src = &d_D2[f * P2 + b * 256];
        float v = -3.4e38f;
        #pragma unroll 8
        for (int j = 0; j < 256; j++) v = fmaxf(v, src[j]);
        out[b * Fv + f] = fmaxf(v + gpb3[f], 0.f);
    }
}

// ---------------- host launcher ----------------
extern "C" void kernel_launch(void* const* d_in, const int* in_sizes, int n_in,
                              void* d_out, int out_size) {
    const float* x    = (const float*)d_in[0];
    const float* node = (const float*)d_in[2];
    const float* fpW0 = (const float*)d_in[4];  const float* fpb0 = (const float*)d_in[5];
    const float* fpW1 = (const float*)d_in[6];  const float* fpb1 = (const float*)d_in[7];
    const float* fpW2 = (const float*)d_in[8];  const float* fpb2 = (const float*)d_in[9];
    const float* fpW3 = (const float*)d_in[10]; const float* fpb3 = (const float*)d_in[11];
    const float* gpW0 = (const float*)d_in[12]; const float* gpb0 = (const float*)d_in[13];
    const float* gpW1 = (const float*)d_in[14]; const float* gpb1 = (const float*)d_in[15];
    const float* gpW2 = (const float*)d_in[16]; const float* gpb2 = (const float*)d_in[17];
    const float* gpW3 = (const float*)d_in[18]; const float* gpb3 = (const float*)d_in[19];

    cudaFuncSetAttribute(k_fp_mma, cudaFuncAttributeMaxDynamicSharedMemorySize, SMEM_TC);

    k_fp_mma<<<NBLK, 512, SMEM_TC>>>(x, node, fpW0, fpb0, fpW1, fpb1,
                                     fpW2, fpb2, fpW3, fpb3);
    k_gp<<<NBLK, 256>>>(gpW0, gpb0, gpW1, gpb1, gpW2, gpb2, gpW3, gpb3,
                        (float*)d_out);
}

// round 16
// speedup vs baseline: 1.2679x; 1.2679x over previous
#include <cuda_runtime.h>
#include <cuda_bf16.h>
#include <math.h>
#include <stdint.h>

// ---------------- problem constants ----------------
#define Bv   4
#define Rv   4
#define Nv   4096
#define Mv   64
#define KNv  12288
#define BRv  16
#define P1   196608
#define P2   1024
#define Fv   512
#define TILES64 3072
#define TPB64   192
#define NGROUPS 296

// ---------------- device scratch ----------------
__device__ int   d_topk[Bv * Nv * 3];
__device__ float d_csum[Bv * 2 * Mv];
__device__ float d_ccnt[Bv * Mv];
__device__ float d_g[130 * P2];
__device__ float d_fcol0[BRv * 128];
__device__ float d_A[256 * P2];
__device__ float d_B2[256 * P2];
__device__ float d_C2[512 * P2];
__device__ float d_D2[512 * P2];
__device__ int   d_ctr;

// ---------------- scalar helpers ----------------
__device__ __forceinline__ unsigned long long ffma2(unsigned long long a,
                                                    unsigned long long b,
                                                    unsigned long long c) {
    unsigned long long d;
    asm("fma.rn.f32x2 %0, %1, %2, %3;" : "=l"(d) : "l"(a), "l"(b), "l"(c));
    return d;
}
__device__ __forceinline__ unsigned long long pack2(float lo, float hi) {
    unsigned long long r;
    asm("mov.b64 %0, {%1, %2};" : "=l"(r) : "f"(lo), "f"(hi));
    return r;
}
__device__ __forceinline__ float lo2(unsigned long long a) { return __uint_as_float((unsigned)a); }
__device__ __forceinline__ float hi2(unsigned long long a) { return __uint_as_float((unsigned)(a >> 32)); }

__device__ __forceinline__ void rot_cs(int r, float& c, float& s) {
    float th = 6.2831855f * (float)r * 0.25f;
    c = cosf(th);
    s = sinf(th);
}
__device__ __forceinline__ uint32_t smem_u32(const void* p) {
    uint32_t a;
    asm("{ .reg .u64 t; cvta.to.shared.u64 t, %1; cvt.u32.u64 %0, t; }" : "=r"(a) : "l"(p));
    return a;
}
__device__ __forceinline__ uint32_t swz(uint32_t b) { return b ^ ((b >> 3) & 0x70); }

// ---------------- warp MMA helpers ----------------
__device__ __forceinline__ void ldsm4(uint32_t* r, uint32_t addr) {
    asm volatile("ldmatrix.sync.aligned.m8n8.x4.shared.b16 {%0,%1,%2,%3}, [%4];"
                 : "=r"(r[0]), "=r"(r[1]), "=r"(r[2]), "=r"(r[3]) : "r"(addr));
}
__device__ __forceinline__ void mma16816(float* d, const uint32_t* a, const uint32_t* b) {
    asm volatile("mma.sync.aligned.m16n8k16.row.col.f32.bf16.bf16.f32 "
                 "{%0,%1,%2,%3}, {%4,%5,%6,%7}, {%8,%9}, {%0,%1,%2,%3};"
                 : "+f"(d[0]), "+f"(d[1]), "+f"(d[2]), "+f"(d[3])
                 : "r"(a[0]), "r"(a[1]), "r"(a[2]), "r"(a[3]), "r"(b[0]), "r"(b[1]));
}

template<int NT>
__device__ __forceinline__ void mma3p(float acc[][4], uint32_t aHb, uint32_t aLb,
                                      uint32_t wHb, uint32_t wLb, int mt0, int n0, int lane) {
    const int abase = (lane & 7) + ((lane >> 3) & 1) * 8;
    const int aoff = ((lane >> 4) & 1) * 16;
    const int arow0 = 16 * mt0 + abase;
    const int arow1 = arow0 + 16;
    const int brow = (lane & 7) + (lane >> 4) * 8;
    const int boff = ((lane >> 3) & 1) * 16;
    #pragma unroll
    for (int ks = 0; ks < 4; ks++) {
        uint32_t aH0[4], aL0[4], aH1[4], aL1[4];
        uint32_t a0s = swz((uint32_t)(arow0 * 128 + 32 * ks + aoff));
        uint32_t a1s = swz((uint32_t)(arow1 * 128 + 32 * ks + aoff));
        ldsm4(aH0, aHb + a0s);
        ldsm4(aH1, aHb + a1s);
        ldsm4(aL0, aLb + a0s);
        ldsm4(aL1, aLb + a1s);
        uint32_t roffs[NT / 2];
        uint32_t wf[NT / 2][4];
        #pragma unroll
        for (int u = 0; u < NT / 2; u++) {
            roffs[u] = swz((uint32_t)((n0 + 16 * u + brow) * 128 + 32 * ks + boff));
            ldsm4(wf[u], wHb + roffs[u]);
        }
        #pragma unroll
        for (int u = 0; u < NT / 2; u++) {
            mma16816(acc[2 * u],          aH0, wf[u]); mma16816(acc[2 * u + 1],      aH0, wf[u] + 2);
            mma16816(acc[NT + 2 * u],     aH1, wf[u]); mma16816(acc[NT + 2 * u + 1], aH1, wf[u] + 2);
        }
        #pragma unroll
        for (int u = 0; u < NT / 2; u++) {
            mma16816(acc[2 * u],          aL0, wf[u]); mma16816(acc[2 * u + 1],      aL0, wf[u] + 2);
            mma16816(acc[NT + 2 * u],     aL1, wf[u]); mma16816(acc[NT + 2 * u + 1], aL1, wf[u] + 2);
        }
        #pragma unroll
        for (int u = 0; u < NT / 2; u++)
            ldsm4(wf[u], wLb + roffs[u]);
        #pragma unroll
        for (int u = 0; u < NT / 2; u++) {
            mma16816(acc[2 * u],          aH0, wf[u]); mma16816(acc[2 * u + 1],      aH0, wf[u] + 2);
            mma16816(acc[NT + 2 * u],     aH1, wf[u]); mma16816(acc[NT + 2 * u + 1], aH1, wf[u] + 2);
        }
    }
}

__device__ __forceinline__ void st_pair(uint32_t hB, uint32_t lB, int p, int o,
                                        float v0, float v1) {
    uint32_t h, l;
    asm("cvt.rn.bf16x2.f32 %0, %1, %2;" : "=r"(h) : "f"(v1), "f"(v0));
    float h0 = __uint_as_float(h << 16);
    float h1 = __uint_as_float(h & 0xffff0000u);
    asm("cvt.rn.bf16x2.f32 %0, %1, %2;" : "=r"(l) : "f"(v1 - h1), "f"(v0 - h0));
    uint32_t off = swz((uint32_t)(p * 128 + 2 * o));
    asm volatile("st.shared.b32 [%0], %1;" :: "r"(hB + off), "r"(h) : "memory");
    asm volatile("st.shared.b32 [%0], %1;" :: "r"(lB + off), "r"(l) : "memory");
}

__device__ __forceinline__ void pack_store8(uint32_t addrH, uint32_t addrL, const float* v) {
    uint32_t h[4], l[4];
    #pragma unroll
    for (int q = 0; q < 4; q++) {
        float a = v[2 * q], b = v[2 * q + 1];
        asm("cvt.rn.bf16x2.f32 %0, %1, %2;" : "=r"(h[q]) : "f"(b), "f"(a));
        float ha = __uint_as_float(h[q] << 16);
        float hb = __uint_as_float(h[q] & 0xffff0000u);
        asm("cvt.rn.bf16x2.f32 %0, %1, %2;" : "=r"(l[q]) : "f"(b - hb), "f"(a - ha));
    }
    asm volatile("st.shared.v4.b32 [%0], {%1, %2, %3, %4};"
                 :: "r"(addrH), "r"(h[0]), "r"(h[1]), "r"(h[2]), "r"(h[3]) : "memory");
    asm volatile("st.shared.v4.b32 [%0], {%1, %2, %3, %4};"
                 :: "r"(addrL), "r"(l[0]), "r"(l[1]), "r"(l[2]), "r"(l[3]) : "memory");
}

// ---------------- K0: combined init ----------------
__global__ void k_initz() {
    int i = blockIdx.x * 256 + threadIdx.x;
    if (i == 0) d_ctr = NGROUPS;
    if (i < Bv * 2 * Mv) d_csum[i] = 0.f;
    if (i < Bv * Mv)     d_ccnt[i] = 0.f;
    if (i < 130 * P2)    d_g[i]    = 0.f;
    if (i < 256 * P2) { d_A[i] = 0.f; d_B2[i] = 0.f; }
    d_C2[i] = 0.f;
    d_D2[i] = 0.f;
}

// ---------------- K1: top-3 + cluster accumulation ----------
__global__ void k_topk(const float* __restrict__ x, const float* __restrict__ node) {
    int idx = blockIdx.x * 256 + threadIdx.x;
    if (idx >= Bv * Nv) return;
    int b = idx >> 12, n = idx & (Nv - 1);
    float x0 = x[b * 2 * Nv + n];
    float x1 = x[b * 2 * Nv + Nv + n];
    float d0 = 3.4e38f, d1 = 3.4e38f, d2 = 3.4e38f;
    int   i0 = 0, i1 = 0, i2 = 0;
    #pragma unroll
    for (int m = 0; m < Mv; m++) {
        float dx = x0 - __ldg(&node[b * 2 * Mv + m]);
        float dy = x1 - __ldg(&node[b * 2 * Mv + Mv + m]);
        float d = dx * dx + dy * dy;
        if (d < d0)      { d2 = d1; i2 = i1; d1 = d0; i1 = i0; d0 = d; i0 = m; }
        else if (d < d1) { d2 = d1; i2 = i1; d1 = d;  i1 = m; }
        else if (d < d2) { d2 = d;  i2 = m; }
    }
    int o = idx * 3;
    d_topk[o] = i0; d_topk[o + 1] = i1; d_topk[o + 2] = i2;
    atomicAdd(&d_csum[b * 2 * Mv + i0],      x0);
    atomicAdd(&d_csum[b * 2 * Mv + Mv + i0], x1);
    atomicAdd(&d_ccnt[b * Mv + i0], 1.f);
    atomicAdd(&d_csum[b * 2 * Mv + i1],      x0);
    atomicAdd(&d_csum[b * 2 * Mv + Mv + i1], x1);
    atomicAdd(&d_ccnt[b * Mv + i1], 1.f);
    atomicAdd(&d_csum[b * 2 * Mv + i2],      x0);
    atomicAdd(&d_csum[b * 2 * Mv + Mv + i2], x1);
    atomicAdd(&d_ccnt[b * Mv + i2], 1.f);
}

// ---------------- warp-MMA fused fp block (R14 work-stealing version) ------
#define OW1H  0
#define OW1L  8192
#define OW2H  16384
#define OW2L  32768
#define OW3AH 49152
#define OW3AL 65536
#define OW3BH 81920
#define OW3BL 98304
#define OGRP  114688
#define OW0F  212992
#define OW3X  213504
#define OB0   214528
#define OB1   214784
#define OB2   215040
#define OB3   215552
#define OXS   216064
#define OMS   217088
#define ONRT  217600
#define OTS   225792
#define SMEM_TC 225824

__global__ void __launch_bounds__(512, 1) k_fp_mma(
    const float* __restrict__ x,
    const float* __restrict__ W0, const float* __restrict__ b0,
    const float* __restrict__ W1, const float* __restrict__ b1,
    const float* __restrict__ W2, const float* __restrict__ b2,
    const float* __restrict__ W3, const float* __restrict__ b3)
{
    extern __shared__ __align__(1024) char smc[];
    float* smf = (float*)smc;
    const int tid  = threadIdx.x;
    const int wid  = tid >> 5;
    const int lane = tid & 31;
    const uint32_t sb = smem_u32(smc);

    for (int i = tid; i < 4096; i += 512) {
        int o = i >> 6, k = i & 63;
        float w = W1[o * 64 + k];
        __nv_bfloat16 h = __float2bfloat16(w);
        __nv_bfloat16 l = __float2bfloat16(w - __bfloat162float(h));
        uint32_t off = swz(o * 128 + 2 * k);
        *(__nv_bfloat16*)(smc + OW1H + off) = h;
        *(__nv_bfloat16*)(smc + OW1L + off) = l;
    }
    for (int i = tid; i < 8192; i += 512) {
        int o = i >> 6, k = i & 63;
        float w = W2[o * 64 + k];
        __nv_bfloat16 h = __float2bfloat16(w);
        __nv_bfloat16 l = __float2bfloat16(w - __bfloat162float(h));
        uint32_t off = swz(o * 128 + 2 * k);
        *(__nv_bfloat16*)(smc + OW2H + off) = h;
        *(__nv_bfloat16*)(smc + OW2L + off) = l;
    }
    for (int i = tid; i < 8192; i += 512) {
        int o = i >> 6, k = i & 63;
        float w = W3[o * 130 + 2 + k];
        __nv_bfloat16 h = __float2bfloat16(w);
        __nv_bfloat16 l = __float2bfloat16(w - __bfloat162float(h));
        uint32_t off = swz(o * 128 + 2 * k);
        *(__nv_bfloat16*)(smc + OW3AH + off) = h;
        *(__nv_bfloat16*)(smc + OW3AL + off) = l;
    }
    for (int i = tid; i < 8192; i += 512) {
        int o = i >> 6, k = i & 63;
        float w = W3[o * 130 + 66 + k];
        __nv_bfloat16 h = __float2bfloat16(w);
        __nv_bfloat16 l = __float2bfloat16(w - __bfloat162float(h));
        uint32_t off = swz(o * 128 + 2 * k);
        *(__nv_bfloat16*)(smc + OW3BH + off) = h;
        *(__nv_bfloat16*)(smc + OW3BL + off) = l;
    }
    if (tid < 128) {
        smf[OW0F / 4 + tid] = W0[tid];
        smf[OW3X / 4 + tid]       = W3[tid * 130];
        smf[OW3X / 4 + 128 + tid] = W3[tid * 130 + 1];
        if (tid < 64) { smf[OB0 / 4 + tid] = b0[tid]; smf[OB1 / 4 + tid] = b1[tid]; }
        smf[OB2 / 4 + tid] = b2[tid];
        smf[OB3 / 4 + tid] = b3[tid];
    }
    if (tid < 256) {
        int b = tid >> 6, m = tid & 63;
        float cnt = d_ccnt[b * Mv + m];
        float inv = 1.f / (cnt + 1e-5f);
        float m0 = d_csum[b * 2 * Mv + m]      * inv;
        float m1 = d_csum[b * 2 * Mv + Mv + m] * inv;
        #pragma unroll
        for (int r = 0; r < Rv; r++) {
            float cc, ss; rot_cs(r, cc, ss);
            int br = b * Rv + r;
            smf[ONRT / 4 + br * 128 + m]      = cc * m0 - ss * m1;
            smf[ONRT / 4 + br * 128 + 64 + m] = ss * m0 + cc * m1;
        }
    }
    __syncthreads();

    const int grp  = wid >> 3;
    const int tidg = tid & 255;
    const int wg   = wid & 7;
    const int mp   = wg >> 2;
    const int nq   = wg & 3;
    const int mt0  = 2 * mp;
    const int gq   = lane >> 2;
    const int tq   = lane & 3;

    const uint32_t gb  = sb + OGRP + grp * 49152;
    const uint32_t bAH = gb,          bAL = gb + 8192;
    const uint32_t bRH = gb + 16384,  bRL = gb + 24576;
    const uint32_t bCH = gb + 32768,  bCL = gb + 40960;
    float* xsf = smf + (OXS + grp * 512) / 4;
    int*   ms  = (int*)(smc + OMS + grp * 256);
    int*   tsh = (int*)(smc + OTS + grp * 4);
    const float* nrt = smf + ONRT / 4;
    const int barid = grp + 1;

    #define GBAR() asm volatile("bar.sync %0, 256;" :: "r"(barid) : "memory")

    int t = blockIdx.x * 2 + grp;
    while (t < TILES64) {
        int br = t / TPB64; int tloc = t - br * TPB64; int kn0 = tloc * 64;
        int b = br >> 2, r = br & 3;

        {
            int pp = tidg & 63, q = tidg >> 6;
            int kn = kn0 + pp; int k = kn >> 12; int n = kn & (Nv - 1);
            float x0r = x[b * 2 * Nv + n], x1r = x[b * 2 * Nv + Nv + n];
            float cc, ss; rot_cs(r, cc, ss);
            float xr0 = cc * x0r - ss * x1r;
            float xr1 = ss * x0r + cc * x1r;
            int m = d_topk[(b * Nv + n) * 3 + k];
            float xd0 = xr0 - nrt[br * 128 + m];
            float xd1 = xr1 - nrt[br * 128 + 64 + m];
            if (q == 0) { xsf[pp] = xd0; xsf[64 + pp] = xd1; ms[pp] = m; }
            float v[16];
            #pragma unroll
            for (int j = 0; j < 16; j++) {
                int o = 16 * q + j;
                v[j] = fmaxf(fmaf(smf[OW0F / 4 + 2 * o], xd0,
                             fmaf(smf[OW0F / 4 + 2 * o + 1], xd1, smf[OB0 / 4 + o])), 0.f);
            }
            uint32_t ro = pp * 128 + 32 * q;
            pack_store8(bAH + swz(ro),      bAL + swz(ro),      v);
            pack_store8(bAH + swz(ro + 16), bAL + swz(ro + 16), v + 8);
        }
        GBAR();

        {
            float acc[4][4];
            #pragma unroll
            for (int i = 0; i < 4; i++)
                #pragma unroll
                for (int j = 0; j < 4; j++) acc[i][j] = 0.f;
            int n0 = nq * 16;
            mma3p<2>(acc, bAH, bAL, sb + OW1H, sb + OW1L, mt0, n0, lane);
            #pragma unroll
            for (int mt = 0; mt < 2; mt++) {
                int rp = 16 * (mt0 + mt) + gq;
                #pragma unroll
                for (int nt = 0; nt < 2; nt++) {
                    int o = n0 + 8 * nt + 2 * tq;
                    float bv0 = smf[OB1 / 4 + o], bv1 = smf[OB1 / 4 + o + 1];
                    float* a = acc[mt * 2 + nt];
                    st_pair(bRH, bRL, rp, o,
                            fmaxf(a[0] + bv0, 0.f), fmaxf(a[1] + bv1, 0.f));
                    st_pair(bRH, bRL, rp + 8, o,
                            fmaxf(a[2] + bv0, 0.f), fmaxf(a[3] + bv1, 0.f));
                }
            }
        }
        GBAR();

        {
            float acc[8][4];
            #pragma unroll
            for (int i = 0; i < 8; i++)
                #pragma unroll
                for (int j = 0; j < 4; j++) acc[i][j] = 0.f;
            int n0 = nq * 32;
            mma3p<4>(acc, bRH, bRL, sb + OW2H, sb + OW2L, mt0, n0, lane);
            uint32_t hB = (nq < 2) ? bAH : bCH;
            uint32_t lB = (nq < 2) ? bAL : bCL;
            #pragma unroll
            for (int mt = 0; mt < 2; mt++) {
                int rp = 16 * (mt0 + mt) + gq;
                #pragma unroll
                for (int nt = 0; nt < 4; nt++) {
                    int o = n0 + 8 * nt + 2 * tq;
                    float bv0 = smf[OB2 / 4 + o], bv1 = smf[OB2 / 4 + o + 1];
                    int oc = o & 63;
                    float* a = acc[mt * 4 + nt];
                    st_pair(hB, lB, rp, oc,
                            fmaxf(a[0] + bv0, 0.f), fmaxf(a[1] + bv1, 0.f));
                    st_pair(hB, lB, rp + 8, oc,
                            fmaxf(a[2] + bv0, 0.f), fmaxf(a[3] + bv1, 0.f));
                }
            }
        }
        GBAR();

        {
            float acc[8][4];
            #pragma unroll
            for (int i = 0; i < 8; i++)
                #pragma unroll
                for (int j = 0; j < 4; j++) acc[i][j] = 0.f;
            int n0 = nq * 32;
            mma3p<4>(acc, bAH, bAL, sb + OW3AH, sb + OW3AL, mt0, n0, lane);
            mma3p<4>(acc, bCH, bCL, sb + OW3BH, sb + OW3BL, mt0, n0, lane);

            #pragma unroll
            for (int mt = 0; mt < 2; mt++) {
                int rp = 16 * (mt0 + mt) + gq;
                float x0a = xsf[rp],     x1a = xsf[64 + rp];
                float x0b = xsf[rp + 8], x1b = xsf[64 + rp + 8];
                int ma = ms[rp], mb = ms[rp + 8];
                unsigned* gpa = (unsigned*)&d_g[2 * P2 + br * Mv + ma];
                unsigned* gpb = (unsigned*)&d_g[2 * P2 + br * Mv + mb];
                bool put0 = (tloc == 0 && rp == 0);
                #pragma unroll
                for (int nt = 0; nt < 4; nt++) {
                    int o = n0 + 8 * nt + 2 * tq;
                    float w00 = smf[OW3X / 4 + o],     w10 = smf[OW3X / 4 + 128 + o];
                    float w01 = smf[OW3X / 4 + o + 1], w11 = smf[OW3X / 4 + 128 + o + 1];
                    float bv0 = smf[OB3 / 4 + o],      bv1 = smf[OB3 / 4 + o + 1];
                    float* a = acc[mt * 4 + nt];
                    float v0 = fmaxf(a[0] + bv0 + w00 * x0a + w10 * x1a, 0.f);
                    float v1 = fmaxf(a[1] + bv1 + w01 * x0a + w11 * x1a, 0.f);
                    float v2 = fmaxf(a[2] + bv0 + w00 * x0b + w10 * x1b, 0.f);
                    float v3 = fmaxf(a[3] + bv1 + w01 * x0b + w11 * x1b, 0.f);
                    atomicMax(gpa + o * P2,       __float_as_uint(v0));
                    atomicMax(gpa + (o + 1) * P2, __float_as_uint(v1));
                    atomicMax(gpb + o * P2,       __float_as_uint(v2));
                    atomicMax(gpb + (o + 1) * P2, __float_as_uint(v3));
                    if (put0) { d_fcol0[br * 128 + o] = v0; d_fcol0[br * 128 + o + 1] = v1; }
                }
            }
        }
        if (tidg == 0) *tsh = atomicAdd(&d_ctr, 1);
        GBAR();
        t = *tsh;
    }
    #undef GBAR
}

// fused "g" load: rows 0-1 node_rot computed inline; rows 2-129 with
// empty-cluster fcol0 fallback. Replaces the k_fix kernel.
__device__ __forceinline__ float load_g(int c, int col) {
    int br = col >> 6, m = col & 63;
    int b = br >> 2, r = br & 3;
    float cnt = d_ccnt[b * Mv + m];
    if (c < 2) {
        float inv = 1.f / (cnt + 1e-5f);
        float m0 = d_csum[b * 2 * Mv + m]      * inv;
        float m1 = d_csum[b * 2 * Mv + Mv + m] * inv;
        float cc, ss; rot_cs(r, cc, ss);
        return c ? (ss * m0 + cc * m1) : (cc * m0 - ss * m1);
    }
    if (cnt == 0.f) return d_fcol0[br * 128 + (c - 2)];
    return d_g[c * P2 + col];
}

// ---------------- gp partial GEMM with fused input activation --------------
// mode: 0 = in1 is d_g (use load_g), 1 = in1 raw+bias1 relu.
__global__ void __launch_bounds__(256) k_gemm_part(
    const float* __restrict__ W,
    const float* __restrict__ in1, int C1, const float* __restrict__ bias1, int gmode,
    const float* __restrict__ in2, int C2, const float* __restrict__ bias2,
    float* __restrict__ out, int KCH)
{
    __shared__ __align__(16) float Wsh[16][68];
    __shared__ __align__(16) float Ish[16][68];
    const int C = C1 + C2;
    const int col0 = blockIdx.x * 64, ob0 = blockIdx.y * 64;
    const int kbase = blockIdx.z * KCH;
    const int kend = (kbase + KCH < C) ? (kbase + KCH) : C;
    const int tid = threadIdx.x;
    const int og = tid >> 5;
    const int cg = tid & 31;
    const int o0 = og * 8, p0 = cg * 2;
    unsigned long long acc[8];
    #pragma unroll
    for (int i = 0; i < 8; i++) acc[i] = 0ull;

    for (int k0 = kbase; k0 < kend; k0 += 16) {
        #pragma unroll
        for (int q = 0; q < 4; q++) {
            int l = tid * 4 + q; int oo = l >> 4, kk = l & 15;
            int c = k0 + kk;
            Wsh[kk][oo] = (c < kend) ? W[(ob0 + oo) * C + c] : 0.f;
        }
        #pragma unroll
        for (int q = 0; q < 4; q++) {
            int l = tid * 4 + q; int kk = l >> 6, cc = l & 63;
            int c = k0 + kk;
            float v = 0.f;
            if (c < kend) {
                if (c < C1) {
                    if (gmode) {
                        v = load_g(c, col0 + cc);
                    } else {
                        v = in1[c * P2 + col0 + cc];
                        if (bias1) v = fmaxf(v + bias1[c], 0.f);
                    }
                } else {
                    v = in2[(c - C1) * P2 + col0 + cc];
                    if (bias2) v = fmaxf(v + bias2[c - C1], 0.f);
                }
            }
            Ish[kk][cc] = v;
        }
        __syncthreads();
        #pragma unroll
        for (int kk = 0; kk < 16; kk++) {
            float4 wA = *(const float4*)&Wsh[kk][o0];
            float4 wB = *(const float4*)&Wsh[kk][o0 + 4];
            unsigned long long a = *(const unsigned long long*)&Ish[kk][p0];
            acc[0] = ffma2(pack2(wA.x, wA.x), a, acc[0]);
            acc[1] = ffma2(pack2(wA.y, wA.y), a, acc[1]);
            acc[2] = ffma2(pack2(wA.z, wA.z), a, acc[2]);
            acc[3] = ffma2(pack2(wA.w, wA.w), a, acc[3]);
            acc[4] = ffma2(pack2(wB.x, wB.x), a, acc[4]);
            acc[5] = ffma2(pack2(wB.y, wB.y), a, acc[5]);
            acc[6] = ffma2(pack2(wB.z, wB.z), a, acc[6]);
            acc[7] = ffma2(pack2(wB.w, wB.w), a, acc[7]);
        }
        __syncthreads();
    }
    #pragma unroll
    for (int i = 0; i < 8; i++) {
        int o = ob0 + o0 + i;
        atomicAdd(&out[o * P2 + col0 + p0],     lo2(acc[i]));
        atomicAdd(&out[o * P2 + col0 + p0 + 1], hi2(acc[i]));
    }
}

// ---------------- K6: final max over (r, m) with fused bias+relu -----------
__global__ void k_reduce(const float* __restrict__ b3, float* __restrict__ out) {
    int idx = blockIdx.x * 256 + threadIdx.x;
    int b = idx >> 9, f = idx & 511;
    const float* src = &d_D2[f * P2 + b * 256];
    float v = -3.4e38f;
    #pragma unroll 8
    for (int j = 0; j < 256; j++) v = fmaxf(v, src[j]);
    out[b * Fv + f] = fmaxf(v + b3[f], 0.f);
}

// ---------------- host launcher ----------------
extern "C" void kernel_launch(void* const* d_in, const int* in_sizes, int n_in,
                              void* d_out, int out_size) {
    const float* x    = (const float*)d_in[0];
    const float* node = (const float*)d_in[2];
    const float* fpW0 = (const float*)d_in[4];  const float* fpb0 = (const float*)d_in[5];
    const float* fpW1 = (const float*)d_in[6];  const float* fpb1 = (const float*)d_in[7];
    const float* fpW2 = (const float*)d_in[8];  const float* fpb2 = (const float*)d_in[9];
    const float* fpW3 = (const float*)d_in[10]; const float* fpb3 = (const float*)d_in[11];
    const float* gpW0 = (const float*)d_in[12]; const float* gpb0 = (const float*)d_in[13];
    const float* gpW1 = (const float*)d_in[14]; const float* gpb1 = (const float*)d_in[15];
    const float* gpW2 = (const float*)d_in[16]; const float* gpb2 = (const float*)d_in[17];
    const float* gpW3 = (const float*)d_in[18]; const float* gpb3 = (const float*)d_in[19];

    float *p_g, *p_A, *p_B2, *p_C2, *p_D2;
    cudaGetSymbolAddress((void**)&p_g,  d_g);
    cudaGetSymbolAddress((void**)&p_A,  d_A);
    cudaGetSymbolAddress((void**)&p_B2, d_B2);
    cudaGetSymbolAddress((void**)&p_C2, d_C2);
    cudaGetSymbolAddress((void**)&p_D2, d_D2);

    cudaFuncSetAttribute(k_fp_mma, cudaFuncAttributeMaxDynamicSharedMemorySize, SMEM_TC);

    k_initz<<<(512 * P2) / 256, 256>>>();
    k_topk<<<(Bv * Nv) / 256, 256>>>(x, node);

    k_fp_mma<<<148, 512, SMEM_TC>>>(x, fpW0, fpb0, fpW1, fpb1,
                                    fpW2, fpb2, fpW3, fpb3);

    // gp block: k-split partial GEMMs, g-fix + activations fused at load
    k_gemm_part<<<dim3(16, 4, 2), 256>>>(gpW0, p_g,  130, nullptr, 1,
                                         nullptr, 0, nullptr, p_A,  65);
    k_gemm_part<<<dim3(16, 4, 4), 256>>>(gpW1, p_A,  256, gpb0, 0,
                                         nullptr, 0, nullptr, p_B2, 64);
    k_gemm_part<<<dim3(16, 8, 4), 256>>>(gpW2, p_B2, 256, gpb1, 0,
                                         nullptr, 0, nullptr, p_C2, 64);
    k_gemm_part<<<dim3(16, 8, 5), 256>>>(gpW3, p_g,  130, nullptr, 1,
                                         p_C2, 512, gpb2, p_D2, 129);

    k_reduce<<<(Bv * Fv) / 256, 256>>>(gpb3, (float*)d_out);
}

// round 17
// speedup vs baseline: 1.3278x; 1.0472x over previous
#include <cuda_runtime.h>
#include <cuda_bf16.h>
#include <math.h>
#include <stdint.h>

// ---------------- problem constants ----------------
#define Bv   4
#define Rv   4
#define Nv   4096
#define Mv   64
#define KNv  12288
#define BRv  16
#define P1   196608
#define P2   1024
#define Fv   512
#define TILES64 3072
#define TPB64   192
#define NGROUPS 296

// ---------------- device scratch ----------------
__device__ int   d_topk[Bv * Nv * 3];
__device__ float d_csum[Bv * 2 * Mv];
__device__ float d_ccnt[Bv * Mv];
__device__ float d_g[130 * P2];
__device__ float d_fcol0[BRv * 128];
__device__ float d_A[256 * P2];
__device__ float d_B2[256 * P2];
__device__ float d_C2[512 * P2];
__device__ float d_D2[512 * P2];
__device__ int   d_ctr;

// ---------------- scalar helpers ----------------
__device__ __forceinline__ unsigned long long ffma2(unsigned long long a,
                                                    unsigned long long b,
                                                    unsigned long long c) {
    unsigned long long d;
    asm("fma.rn.f32x2 %0, %1, %2, %3;" : "=l"(d) : "l"(a), "l"(b), "l"(c));
    return d;
}
__device__ __forceinline__ unsigned long long pack2(float lo, float hi) {
    unsigned long long r;
    asm("mov.b64 %0, {%1, %2};" : "=l"(r) : "f"(lo), "f"(hi));
    return r;
}
__device__ __forceinline__ float lo2(unsigned long long a) { return __uint_as_float((unsigned)a); }
__device__ __forceinline__ float hi2(unsigned long long a) { return __uint_as_float((unsigned)(a >> 32)); }

__device__ __forceinline__ void rot_cs(int r, float& c, float& s) {
    float th = 6.2831855f * (float)r * 0.25f;
    c = cosf(th);
    s = sinf(th);
}
__device__ __forceinline__ uint32_t smem_u32(const void* p) {
    uint32_t a;
    asm("{ .reg .u64 t; cvta.to.shared.u64 t, %1; cvt.u32.u64 %0, t; }" : "=r"(a) : "l"(p));
    return a;
}
__device__ __forceinline__ uint32_t swz(uint32_t b) { return b ^ ((b >> 3) & 0x70); }

// ---------------- warp MMA helpers ----------------
__device__ __forceinline__ void ldsm4(uint32_t* r, uint32_t addr) {
    asm volatile("ldmatrix.sync.aligned.m8n8.x4.shared.b16 {%0,%1,%2,%3}, [%4];"
                 : "=r"(r[0]), "=r"(r[1]), "=r"(r[2]), "=r"(r[3]) : "r"(addr));
}
__device__ __forceinline__ void mma16816(float* d, const uint32_t* a, const uint32_t* b) {
    asm volatile("mma.sync.aligned.m16n8k16.row.col.f32.bf16.bf16.f32 "
                 "{%0,%1,%2,%3}, {%4,%5,%6,%7}, {%8,%9}, {%0,%1,%2,%3};"
                 : "+f"(d[0]), "+f"(d[1]), "+f"(d[2]), "+f"(d[3])
                 : "r"(a[0]), "r"(a[1]), "r"(a[2]), "r"(a[3]), "r"(b[0]), "r"(b[1]));
}

template<int NT>
__device__ __forceinline__ void mma3p(float acc[][4], uint32_t aHb, uint32_t aLb,
                                      uint32_t wHb, uint32_t wLb, int mt0, int n0, int lane) {
    const int abase = (lane & 7) + ((lane >> 3) & 1) * 8;
    const int aoff = ((lane >> 4) & 1) * 16;
    const int arow0 = 16 * mt0 + abase;
    const int arow1 = arow0 + 16;
    const int brow = (lane & 7) + (lane >> 4) * 8;
    const int boff = ((lane >> 3) & 1) * 16;
    #pragma unroll
    for (int ks = 0; ks < 4; ks++) {
        uint32_t aH0[4], aL0[4], aH1[4], aL1[4];
        uint32_t a0s = swz((uint32_t)(arow0 * 128 + 32 * ks + aoff));
        uint32_t a1s = swz((uint32_t)(arow1 * 128 + 32 * ks + aoff));
        ldsm4(aH0, aHb + a0s);
        ldsm4(aH1, aHb + a1s);
        ldsm4(aL0, aLb + a0s);
        ldsm4(aL1, aLb + a1s);
        uint32_t roffs[NT / 2];
        uint32_t wf[NT / 2][4];
        #pragma unroll
        for (int u = 0; u < NT / 2; u++) {
            roffs[u] = swz((uint32_t)((n0 + 16 * u + brow) * 128 + 32 * ks + boff));
            ldsm4(wf[u], wHb + roffs[u]);
        }
        #pragma unroll
        for (int u = 0; u < NT / 2; u++) {
            mma16816(acc[2 * u],          aH0, wf[u]); mma16816(acc[2 * u + 1],      aH0, wf[u] + 2);
            mma16816(acc[NT + 2 * u],     aH1, wf[u]); mma16816(acc[NT + 2 * u + 1], aH1, wf[u] + 2);
        }
        #pragma unroll
        for (int u = 0; u < NT / 2; u++) {
            mma16816(acc[2 * u],          aL0, wf[u]); mma16816(acc[2 * u + 1],      aL0, wf[u] + 2);
            mma16816(acc[NT + 2 * u],     aL1, wf[u]); mma16816(acc[NT + 2 * u + 1], aL1, wf[u] + 2);
        }
        #pragma unroll
        for (int u = 0; u < NT / 2; u++)
            ldsm4(wf[u], wLb + roffs[u]);
        #pragma unroll
        for (int u = 0; u < NT / 2; u++) {
            mma16816(acc[2 * u],          aH0, wf[u]); mma16816(acc[2 * u + 1],      aH0, wf[u] + 2);
            mma16816(acc[NT + 2 * u],     aH1, wf[u]); mma16816(acc[NT + 2 * u + 1], aH1, wf[u] + 2);
        }
    }
}

__device__ __forceinline__ void st_pair(uint32_t hB, uint32_t lB, int p, int o,
                                        float v0, float v1) {
    uint32_t h, l;
    asm("cvt.rn.bf16x2.f32 %0, %1, %2;" : "=r"(h) : "f"(v1), "f"(v0));
    float h0 = __uint_as_float(h << 16);
    float h1 = __uint_as_float(h & 0xffff0000u);
    asm("cvt.rn.bf16x2.f32 %0, %1, %2;" : "=r"(l) : "f"(v1 - h1), "f"(v0 - h0));
    uint32_t off = swz((uint32_t)(p * 128 + 2 * o));
    asm volatile("st.shared.b32 [%0], %1;" :: "r"(hB + off), "r"(h) : "memory");
    asm volatile("st.shared.b32 [%0], %1;" :: "r"(lB + off), "r"(l) : "memory");
}

__device__ __forceinline__ void pack_store8(uint32_t addrH, uint32_t addrL, const float* v) {
    uint32_t h[4], l[4];
    #pragma unroll
    for (int q = 0; q < 4; q++) {
        float a = v[2 * q], b = v[2 * q + 1];
        asm("cvt.rn.bf16x2.f32 %0, %1, %2;" : "=r"(h[q]) : "f"(b), "f"(a));
        float ha = __uint_as_float(h[q] << 16);
        float hb = __uint_as_float(h[q] & 0xffff0000u);
        asm("cvt.rn.bf16x2.f32 %0, %1, %2;" : "=r"(l[q]) : "f"(b - hb), "f"(a - ha));
    }
    asm volatile("st.shared.v4.b32 [%0], {%1, %2, %3, %4};"
                 :: "r"(addrH), "r"(h[0]), "r"(h[1]), "r"(h[2]), "r"(h[3]) : "memory");
    asm volatile("st.shared.v4.b32 [%0], {%1, %2, %3, %4};"
                 :: "r"(addrL), "r"(l[0]), "r"(l[1]), "r"(l[2]), "r"(l[3]) : "memory");
}

// ---------------- K0: combined init ----------------
__global__ void k_initz() {
    int i = blockIdx.x * 256 + threadIdx.x;
    if (i == 0) d_ctr = NGROUPS;
    if (i < Bv * 2 * Mv) d_csum[i] = 0.f;
    if (i < Bv * Mv)     d_ccnt[i] = 0.f;
    if (i < 130 * P2)    d_g[i]    = 0.f;
    if (i < 256 * P2) { d_A[i] = 0.f; d_B2[i] = 0.f; }
    d_C2[i] = 0.f;
    d_D2[i] = 0.f;
}

// ---------------- K1: top-3 + cluster accumulation ----------
__global__ void k_topk(const float* __restrict__ x, const float* __restrict__ node) {
    int idx = blockIdx.x * 256 + threadIdx.x;
    if (idx >= Bv * Nv) return;
    int b = idx >> 12, n = idx & (Nv - 1);
    float x0 = x[b * 2 * Nv + n];
    float x1 = x[b * 2 * Nv + Nv + n];
    float d0 = 3.4e38f, d1 = 3.4e38f, d2 = 3.4e38f;
    int   i0 = 0, i1 = 0, i2 = 0;
    #pragma unroll
    for (int m = 0; m < Mv; m++) {
        float dx = x0 - __ldg(&node[b * 2 * Mv + m]);
        float dy = x1 - __ldg(&node[b * 2 * Mv + Mv + m]);
        float d = dx * dx + dy * dy;
        if (d < d0)      { d2 = d1; i2 = i1; d1 = d0; i1 = i0; d0 = d; i0 = m; }
        else if (d < d1) { d2 = d1; i2 = i1; d1 = d;  i1 = m; }
        else if (d < d2) { d2 = d;  i2 = m; }
    }
    int o = idx * 3;
    d_topk[o] = i0; d_topk[o + 1] = i1; d_topk[o + 2] = i2;
    atomicAdd(&d_csum[b * 2 * Mv + i0],      x0);
    atomicAdd(&d_csum[b * 2 * Mv + Mv + i0], x1);
    atomicAdd(&d_ccnt[b * Mv + i0], 1.f);
    atomicAdd(&d_csum[b * 2 * Mv + i1],      x0);
    atomicAdd(&d_csum[b * 2 * Mv + Mv + i1], x1);
    atomicAdd(&d_ccnt[b * Mv + i1], 1.f);
    atomicAdd(&d_csum[b * 2 * Mv + i2],      x0);
    atomicAdd(&d_csum[b * 2 * Mv + Mv + i2], x1);
    atomicAdd(&d_ccnt[b * Mv + i2], 1.f);
}

// ---------------- warp-MMA fused fp block (work-stealing) -------------------
#define OW1H  0
#define OW1L  8192
#define OW2H  16384
#define OW2L  32768
#define OW3AH 49152
#define OW3AL 65536
#define OW3BH 81920
#define OW3BL 98304
#define OGRP  114688
#define OW0F  212992
#define OW3X  213504
#define OB0   214528
#define OB1   214784
#define OB2   215040
#define OB3   215552
#define OXS   216064
#define OMS   217088
#define ONRT  217600
#define OTS   225792
#define SMEM_TC 225824

__global__ void __launch_bounds__(512, 1) k_fp_mma(
    const float* __restrict__ x,
    const float* __restrict__ W0, const float* __restrict__ b0,
    const float* __restrict__ W1, const float* __restrict__ b1,
    const float* __restrict__ W2, const float* __restrict__ b2,
    const float* __restrict__ W3, const float* __restrict__ b3)
{
    extern __shared__ __align__(1024) char smc[];
    float* smf = (float*)smc;
    const int tid  = threadIdx.x;
    const int wid  = tid >> 5;
    const int lane = tid & 31;
    const uint32_t sb = smem_u32(smc);

    for (int i = tid; i < 4096; i += 512) {
        int o = i >> 6, k = i & 63;
        float w = W1[o * 64 + k];
        __nv_bfloat16 h = __float2bfloat16(w);
        __nv_bfloat16 l = __float2bfloat16(w - __bfloat162float(h));
        uint32_t off = swz(o * 128 + 2 * k);
        *(__nv_bfloat16*)(smc + OW1H + off) = h;
        *(__nv_bfloat16*)(smc + OW1L + off) = l;
    }
    for (int i = tid; i < 8192; i += 512) {
        int o = i >> 6, k = i & 63;
        float w = W2[o * 64 + k];
        __nv_bfloat16 h = __float2bfloat16(w);
        __nv_bfloat16 l = __float2bfloat16(w - __bfloat162float(h));
        uint32_t off = swz(o * 128 + 2 * k);
        *(__nv_bfloat16*)(smc + OW2H + off) = h;
        *(__nv_bfloat16*)(smc + OW2L + off) = l;
    }
    for (int i = tid; i < 8192; i += 512) {
        int o = i >> 6, k = i & 63;
        float w = W3[o * 130 + 2 + k];
        __nv_bfloat16 h = __float2bfloat16(w);
        __nv_bfloat16 l = __float2bfloat16(w - __bfloat162float(h));
        uint32_t off = swz(o * 128 + 2 * k);
        *(__nv_bfloat16*)(smc + OW3AH + off) = h;
        *(__nv_bfloat16*)(smc + OW3AL + off) = l;
    }
    for (int i = tid; i < 8192; i += 512) {
        int o = i >> 6, k = i & 63;
        float w = W3[o * 130 + 66 + k];
        __nv_bfloat16 h = __float2bfloat16(w);
        __nv_bfloat16 l = __float2bfloat16(w - __bfloat162float(h));
        uint32_t off = swz(o * 128 + 2 * k);
        *(__nv_bfloat16*)(smc + OW3BH + off) = h;
        *(__nv_bfloat16*)(smc + OW3BL + off) = l;
    }
    if (tid < 128) {
        smf[OW0F / 4 + tid] = W0[tid];
        smf[OW3X / 4 + tid]       = W3[tid * 130];
        smf[OW3X / 4 + 128 + tid] = W3[tid * 130 + 1];
        if (tid < 64) { smf[OB0 / 4 + tid] = b0[tid]; smf[OB1 / 4 + tid] = b1[tid]; }
        smf[OB2 / 4 + tid] = b2[tid];
        smf[OB3 / 4 + tid] = b3[tid];
    }
    if (tid < 256) {
        int b = tid >> 6, m = tid & 63;
        float cnt = d_ccnt[b * Mv + m];
        float inv = 1.f / (cnt + 1e-5f);
        float m0 = d_csum[b * 2 * Mv + m]      * inv;
        float m1 = d_csum[b * 2 * Mv + Mv + m] * inv;
        #pragma unroll
        for (int r = 0; r < Rv; r++) {
            float cc, ss; rot_cs(r, cc, ss);
            int br = b * Rv + r;
            smf[ONRT / 4 + br * 128 + m]      = cc * m0 - ss * m1;
            smf[ONRT / 4 + br * 128 + 64 + m] = ss * m0 + cc * m1;
        }
    }
    __syncthreads();

    const int grp  = wid >> 3;
    const int tidg = tid & 255;
    const int wg   = wid & 7;
    const int mp   = wg >> 2;
    const int nq   = wg & 3;
    const int mt0  = 2 * mp;
    const int gq   = lane >> 2;
    const int tq   = lane & 3;

    const uint32_t gb  = sb + OGRP + grp * 49152;
    const uint32_t bAH = gb,          bAL = gb + 8192;
    const uint32_t bRH = gb + 16384,  bRL = gb + 24576;
    const uint32_t bCH = gb + 32768,  bCL = gb + 40960;
    float* xsf = smf + (OXS + grp * 512) / 4;
    int*   ms  = (int*)(smc + OMS + grp * 256);
    int*   tsh = (int*)(smc + OTS + grp * 4);
    const float* nrt = smf + ONRT / 4;
    const int barid = grp + 1;

    #define GBAR() asm volatile("bar.sync %0, 256;" :: "r"(barid) : "memory")

    int t = blockIdx.x * 2 + grp;
    while (t < TILES64) {
        int br = t / TPB64; int tloc = t - br * TPB64; int kn0 = tloc * 64;
        int b = br >> 2, r = br & 3;

        {
            int pp = tidg & 63, q = tidg >> 6;
            int kn = kn0 + pp; int k = kn >> 12; int n = kn & (Nv - 1);
            float x0r = x[b * 2 * Nv + n], x1r = x[b * 2 * Nv + Nv + n];
            float cc, ss; rot_cs(r, cc, ss);
            float xr0 = cc * x0r - ss * x1r;
            float xr1 = ss * x0r + cc * x1r;
            int m = d_topk[(b * Nv + n) * 3 + k];
            float xd0 = xr0 - nrt[br * 128 + m];
            float xd1 = xr1 - nrt[br * 128 + 64 + m];
            if (q == 0) { xsf[pp] = xd0; xsf[64 + pp] = xd1; ms[pp] = m; }
            float v[16];
            #pragma unroll
            for (int j = 0; j < 16; j++) {
                int o = 16 * q + j;
                v[j] = fmaxf(fmaf(smf[OW0F / 4 + 2 * o], xd0,
                             fmaf(smf[OW0F / 4 + 2 * o + 1], xd1, smf[OB0 / 4 + o])), 0.f);
            }
            uint32_t ro = pp * 128 + 32 * q;
            pack_store8(bAH + swz(ro),      bAL + swz(ro),      v);
            pack_store8(bAH + swz(ro + 16), bAL + swz(ro + 16), v + 8);
        }
        GBAR();

        {
            float acc[4][4];
            #pragma unroll
            for (int i = 0; i < 4; i++)
                #pragma unroll
                for (int j = 0; j < 4; j++) acc[i][j] = 0.f;
            int n0 = nq * 16;
            mma3p<2>(acc, bAH, bAL, sb + OW1H, sb + OW1L, mt0, n0, lane);
            #pragma unroll
            for (int mt = 0; mt < 2; mt++) {
                int rp = 16 * (mt0 + mt) + gq;
                #pragma unroll
                for (int nt = 0; nt < 2; nt++) {
                    int o = n0 + 8 * nt + 2 * tq;
                    float bv0 = smf[OB1 / 4 + o], bv1 = smf[OB1 / 4 + o + 1];
                    float* a = acc[mt * 2 + nt];
                    st_pair(bRH, bRL, rp, o,
                            fmaxf(a[0] + bv0, 0.f), fmaxf(a[1] + bv1, 0.f));
                    st_pair(bRH, bRL, rp + 8, o,
                            fmaxf(a[2] + bv0, 0.f), fmaxf(a[3] + bv1, 0.f));
                }
            }
        }
        GBAR();

        {
            float acc[8][4];
            #pragma unroll
            for (int i = 0; i < 8; i++)
                #pragma unroll
                for (int j = 0; j < 4; j++) acc[i][j] = 0.f;
            int n0 = nq * 32;
            mma3p<4>(acc, bRH, bRL, sb + OW2H, sb + OW2L, mt0, n0, lane);
            uint32_t hB = (nq < 2) ? bAH : bCH;
            uint32_t lB = (nq < 2) ? bAL : bCL;
            #pragma unroll
            for (int mt = 0; mt < 2; mt++) {
                int rp = 16 * (mt0 + mt) + gq;
                #pragma unroll
                for (int nt = 0; nt < 4; nt++) {
                    int o = n0 + 8 * nt + 2 * tq;
                    float bv0 = smf[OB2 / 4 + o], bv1 = smf[OB2 / 4 + o + 1];
                    int oc = o & 63;
                    float* a = acc[mt * 4 + nt];
                    st_pair(hB, lB, rp, oc,
                            fmaxf(a[0] + bv0, 0.f), fmaxf(a[1] + bv1, 0.f));
                    st_pair(hB, lB, rp + 8, oc,
                            fmaxf(a[2] + bv0, 0.f), fmaxf(a[3] + bv1, 0.f));
                }
            }
        }
        GBAR();

        {
            float acc[8][4];
            #pragma unroll
            for (int i = 0; i < 8; i++)
                #pragma unroll
                for (int j = 0; j < 4; j++) acc[i][j] = 0.f;
            int n0 = nq * 32;
            mma3p<4>(acc, bAH, bAL, sb + OW3AH, sb + OW3AL, mt0, n0, lane);
            mma3p<4>(acc, bCH, bCL, sb + OW3BH, sb + OW3BL, mt0, n0, lane);

            #pragma unroll
            for (int mt = 0; mt < 2; mt++) {
                int rp = 16 * (mt0 + mt) + gq;
                float x0a = xsf[rp],     x1a = xsf[64 + rp];
                float x0b = xsf[rp + 8], x1b = xsf[64 + rp + 8];
                int ma = ms[rp], mb = ms[rp + 8];
                unsigned* gpa = (unsigned*)&d_g[2 * P2 + br * Mv + ma];
                unsigned* gpb = (unsigned*)&d_g[2 * P2 + br * Mv + mb];
                bool put0 = (tloc == 0 && rp == 0);
                #pragma unroll
                for (int nt = 0; nt < 4; nt++) {
                    int o = n0 + 8 * nt + 2 * tq;
                    float w00 = smf[OW3X / 4 + o],     w10 = smf[OW3X / 4 + 128 + o];
                    float w01 = smf[OW3X / 4 + o + 1], w11 = smf[OW3X / 4 + 128 + o + 1];
                    float bv0 = smf[OB3 / 4 + o],      bv1 = smf[OB3 / 4 + o + 1];
                    float* a = acc[mt * 4 + nt];
                    float v0 = fmaxf(a[0] + bv0 + w00 * x0a + w10 * x1a, 0.f);
                    float v1 = fmaxf(a[1] + bv1 + w01 * x0a + w11 * x1a, 0.f);
                    float v2 = fmaxf(a[2] + bv0 + w00 * x0b + w10 * x1b, 0.f);
                    float v3 = fmaxf(a[3] + bv1 + w01 * x0b + w11 * x1b, 0.f);
                    atomicMax(gpa + o * P2,       __float_as_uint(v0));
                    atomicMax(gpa + (o + 1) * P2, __float_as_uint(v1));
                    atomicMax(gpb + o * P2,       __float_as_uint(v2));
                    atomicMax(gpb + (o + 1) * P2, __float_as_uint(v3));
                    if (put0) { d_fcol0[br * 128 + o] = v0; d_fcol0[br * 128 + o + 1] = v1; }
                }
            }
        }
        if (tidg == 0) *tsh = atomicAdd(&d_ctr, 1);
        GBAR();
        t = *tsh;
    }
    #undef GBAR
}

// ---------------- K5: empty-cluster fallback + d_g rows 0/1 ----------------
__global__ void k_fix() {
    int idx = blockIdx.x * 256 + threadIdx.x;
    if (idx < 2048) {
        int m = idx & 63, br = (idx >> 6) & 15, ch = idx >> 10;
        int b = br >> 2, r = br & 3;
        float cnt = d_ccnt[b * Mv + m];
        float inv = 1.f / (cnt + 1e-5f);
        float m0 = d_csum[b * 2 * Mv + m]      * inv;
        float m1 = d_csum[b * 2 * Mv + Mv + m] * inv;
        float cc, ss; rot_cs(r, cc, ss);
        d_g[ch * P2 + br * Mv + m] = ch ? (ss * m0 + cc * m1) : (cc * m0 - ss * m1);
    }
    int m = idx & 63; int c = (idx >> 6) & 127; int br = idx >> 13;
    int b = br >> 2;
    if (d_ccnt[b * Mv + m] == 0.f)
        d_g[(2 + c) * P2 + br * Mv + m] = d_fcol0[br * 128 + c];
}

// ---------------- gp partial GEMM with fused input activation --------------
__global__ void __launch_bounds__(256) k_gemm_part(
    const float* __restrict__ W,
    const float* __restrict__ in1, int C1, const float* __restrict__ bias1,
    const float* __restrict__ in2, int C2, const float* __restrict__ bias2,
    float* __restrict__ out, int KCH)
{
    __shared__ __align__(16) float Wsh[16][68];
    __shared__ __align__(16) float Ish[16][68];
    const int C = C1 + C2;
    const int col0 = blockIdx.x * 64, ob0 = blockIdx.y * 64;
    const int kbase = blockIdx.z * KCH;
    const int kend = (kbase + KCH < C) ? (kbase + KCH) : C;
    const int tid = threadIdx.x;
    const int og = tid >> 5;
    const int cg = tid & 31;
    const int o0 = og * 8, p0 = cg * 2;
    unsigned long long acc[8];
    #pragma unroll
    for (int i = 0; i < 8; i++) acc[i] = 0ull;

    for (int k0 = kbase; k0 < kend; k0 += 16) {
        #pragma unroll
        for (int q = 0; q < 4; q++) {
            int l = tid * 4 + q; int oo = l >> 4, kk = l & 15;
            int c = k0 + kk;
            Wsh[kk][oo] = (c < kend) ? W[(ob0 + oo) * C + c] : 0.f;
        }
        #pragma unroll
        for (int q = 0; q < 4; q++) {
            int l = tid * 4 + q; int kk = l >> 6, cc = l & 63;
            int c = k0 + kk;
            float v = 0.f;
            if (c < kend) {
                if (c < C1) {
                    v = in1[c * P2 + col0 + cc];
                    if (bias1) v = fmaxf(v + bias1[c], 0.f);
                } else {
                    v = in2[(c - C1) * P2 + col0 + cc];
                    if (bias2) v = fmaxf(v + bias2[c - C1], 0.f);
                }
            }
            Ish[kk][cc] = v;
        }
        __syncthreads();
        #pragma unroll
        for (int kk = 0; kk < 16; kk++) {
            float4 wA = *(const float4*)&Wsh[kk][o0];
            float4 wB = *(const float4*)&Wsh[kk][o0 + 4];
            unsigned long long a = *(const unsigned long long*)&Ish[kk][p0];
            acc[0] = ffma2(pack2(wA.x, wA.x), a, acc[0]);
            acc[1] = ffma2(pack2(wA.y, wA.y), a, acc[1]);
            acc[2] = ffma2(pack2(wA.z, wA.z), a, acc[2]);
            acc[3] = ffma2(pack2(wA.w, wA.w), a, acc[3]);
            acc[4] = ffma2(pack2(wB.x, wB.x), a, acc[4]);
            acc[5] = ffma2(pack2(wB.y, wB.y), a, acc[5]);
            acc[6] = ffma2(pack2(wB.z, wB.z), a, acc[6]);
            acc[7] = ffma2(pack2(wB.w, wB.w), a, acc[7]);
        }
        __syncthreads();
    }
    #pragma unroll
    for (int i = 0; i < 8; i++) {
        int o = ob0 + o0 + i;
        atomicAdd(&out[o * P2 + col0 + p0],     lo2(acc[i]));
        atomicAdd(&out[o * P2 + col0 + p0 + 1], hi2(acc[i]));
    }
}

// ---------------- K6: final max over (r, m) with fused bias+relu -----------
__global__ void k_reduce(const float* __restrict__ b3, float* __restrict__ out) {
    int idx = blockIdx.x * 256 + threadIdx.x;
    int b = idx >> 9, f = idx & 511;
    const float* src = &d_D2[f * P2 + b * 256];
    float v = -3.4e38f;
    #pragma unroll 8
    for (int j = 0; j < 256; j++) v = fmaxf(v, src[j]);
    out[b * Fv + f] = fmaxf(v + b3[f], 0.f);
}

// ---------------- host launcher ----------------
extern "C" void kernel_launch(void* const* d_in, const int* in_sizes, int n_in,
                              void* d_out, int out_size) {
    const float* x    = (const float*)d_in[0];
    const float* node = (const float*)d_in[2];
    const float* fpW0 = (const float*)d_in[4];  const float* fpb0 = (const float*)d_in[5];
    const float* fpW1 = (const float*)d_in[6];  const float* fpb1 = (const float*)d_in[7];
    const float* fpW2 = (const float*)d_in[8];  const float* fpb2 = (const float*)d_in[9];
    const float* fpW3 = (const float*)d_in[10]; const float* fpb3 = (const float*)d_in[11];
    const float* gpW0 = (const float*)d_in[12]; const float* gpb0 = (const float*)d_in[13];
    const float* gpW1 = (const float*)d_in[14]; const float* gpb1 = (const float*)d_in[15];
    const float* gpW2 = (const float*)d_in[16]; const float* gpb2 = (const float*)d_in[17];
    const float* gpW3 = (const float*)d_in[18]; const float* gpb3 = (const float*)d_in[19];

    float *p_g, *p_A, *p_B2, *p_C2, *p_D2;
    cudaGetSymbolAddress((void**)&p_g,  d_g);
    cudaGetSymbolAddress((void**)&p_A,  d_A);
    cudaGetSymbolAddress((void**)&p_B2, d_B2);
    cudaGetSymbolAddress((void**)&p_C2, d_C2);
    cudaGetSymbolAddress((void**)&p_D2, d_D2);

    cudaFuncSetAttribute(k_fp_mma, cudaFuncAttributeMaxDynamicSharedMemorySize, SMEM_TC);

    k_initz<<<(512 * P2) / 256, 256>>>();
    k_topk<<<(Bv * Nv) / 256, 256>>>(x, node);

    k_fp_mma<<<148, 512, SMEM_TC>>>(x, fpW0, fpb0, fpW1, fpb1,
                                    fpW2, fpb2, fpW3, fpb3);
    k_fix<<<(BRv * 128 * Mv) / 256, 256>>>();

    // gp block: k-split partial GEMMs, activations fused at load
    k_gemm_part<<<dim3(16, 4, 2), 256>>>(gpW0, p_g,  130, nullptr,
                                         nullptr, 0, nullptr, p_A,  65);
    k_gemm_part<<<dim3(16, 4, 4), 256>>>(gpW1, p_A,  256, gpb0,
                                         nullptr, 0, nullptr, p_B2, 64);
    k_gemm_part<<<dim3(16, 8, 4), 256>>>(gpW2, p_B2, 256, gpb1,
                                         nullptr, 0, nullptr, p_C2, 64);
    k_gemm_part<<<dim3(16, 8, 5), 256>>>(gpW3, p_g,  130, nullptr,
                                         p_C2, 512, gpb2, p_D2, 129);

    k_reduce<<<(Bv * Fv) / 256, 256>>>(gpb3, (float*)d_out);
}